// round 12
// baseline (speedup 1.0000x reference)
#include <cuda_runtime.h>
#include <cuda_bf16.h>
#include <cstdint>

#define NCARDS 50000
#define NJ 49999
#define B 1024
#define NTOT 51198976ull     // B*NJ
#define JC 38
#define CHUNK 1344
#define NJ_PAD (JC*CHUNK)    // 51072
#define TILES 21
#define LOG2E 1.4426950408889634f
#define KL_EPS 1e-7f
#define LG2_EPS -23.253496664211536f

// smem layout (bytes): Ebuf0[9216] Ebuf1[9216] ADJ0[17408] ADJ1[17408] = 53248
#define ES_STRIDE 144
#define ES_BYTES  9216
#define ADJ_STRIDE 68
#define ADJ_BYTES (64*ADJ_STRIDE*4)   // 17408
#define ADJ_OFF   (2*ES_BYTES)
#define SMEM_BIG  (ADJ_OFF + 2*ADJ_BYTES)  // 53248

// ---------------- device scratch ----------------
__device__ __nv_bfloat16 g_eB [(size_t)NJ_PAD*64];   // E normalized, [j][k]
__device__ __nv_bfloat16 g_eBT[(size_t)64*NJ_PAD];   // E^T, [k][j]
__device__ __nv_bfloat16 g_aBF[B*64];                // t*log2e * normalized a, [b][k]
__device__ float    g_acc[B*4];     // {z, -, t2, t3}
__device__ float    g_G[B*64];      // G = clip(adj) @ E
__device__ unsigned g_minL[B];
__device__ float    g_cross[B], g_lse2[B];
__device__ int      g_flag[B];

// ---------------- helpers ----------------
__device__ __forceinline__ float ex2f_(float x){ float r; asm("ex2.approx.f32 %0, %1;" : "=f"(r) : "f"(x)); return r; }
__device__ __forceinline__ float lg2f_(float x){ float r; asm("lg2.approx.f32 %0, %1;" : "=f"(r) : "f"(x)); return r; }
__device__ __forceinline__ uint32_t smem_u32(const void* p){
    uint32_t a; asm("{ .reg .u64 t; cvta.to.shared.u64 t, %1; cvt.u32.u64 %0, t; }" : "=r"(a) : "l"(p)); return a; }
__device__ __forceinline__ unsigned ford(float f){
    int i = __float_as_int(f);
    return (i >= 0) ? ((unsigned)i | 0x80000000u) : ~(unsigned)i;
}
__device__ __forceinline__ float forddec(unsigned u){
    int i = (u & 0x80000000u) ? (int)(u & 0x7FFFFFFFu) : ~(int)u;
    return __int_as_float(i);
}
__device__ __forceinline__ void mma16816(float* c, const uint32_t* a, uint32_t b0, uint32_t b1){
    asm volatile("mma.sync.aligned.m16n8k16.row.col.f32.bf16.bf16.f32 "
        "{%0,%1,%2,%3}, {%4,%5,%6,%7}, {%8,%9}, {%0,%1,%2,%3};"
        : "+f"(c[0]), "+f"(c[1]), "+f"(c[2]), "+f"(c[3])
        : "r"(a[0]), "r"(a[1]), "r"(a[2]), "r"(a[3]), "r"(b0), "r"(b1));
}
#define LDM4(r0,r1,r2,r3,addr) \
    asm volatile("ldmatrix.sync.aligned.m8n8.x4.shared.b16 {%0,%1,%2,%3}, [%4];" \
        : "=r"(r0), "=r"(r1), "=r"(r2), "=r"(r3) : "r"(addr))
#define CVTB2(d, hi, lo) asm("cvt.rn.bf16x2.f32 %0, %1, %2;" : "=r"(d) : "f"(hi), "f"(lo))

// ---------------- kernel 0: normalize E[1:], write [j][k] AND transposed [k][j] ----------------
__global__ void k_prep(const float* __restrict__ emb){
    __shared__ float sm[64][65];
    __shared__ float inv[64];
    int t = threadIdx.x;
    int jb = blockIdx.x*64;
#pragma unroll
    for(int i=0;i<16;i++){
        int idx = t + i*256; int j = idx>>6, k = idx&63;
        int jg = jb + j;
        sm[j][k] = (jg < NJ) ? emb[(size_t)(jg+1)*64 + k] : 0.f;
    }
    __syncthreads();
    if (t < 64){
        float s = 0.f;
#pragma unroll
        for(int k=0;k<64;k++){ float v = sm[t][k]; s = fmaf(v, v, s); }
        inv[t] = rsqrtf(fmaxf(s, 1e-12f));
    }
    __syncthreads();
#pragma unroll
    for(int i=0;i<16;i++){
        int idx = t + i*256; int j = idx>>6, k = idx&63;
        g_eB[(size_t)(jb+j)*64 + k] = __float2bfloat16_rn(sm[j][k]*inv[j]);
    }
#pragma unroll
    for(int i=0;i<16;i++){
        int idx = t + i*256; int k = idx>>6, j = idx&63;
        g_eBT[(size_t)k*NJ_PAD + jb + j] = __float2bfloat16_rn(sm[j][k]*inv[j]);
    }
}

// ---------------- kernel 1: gather + MLP + l2norm, fold t*log2e ----------------
__global__ void __launch_bounds__(256) k_mlp(const int* __restrict__ cards, const float* __restrict__ emb,
        const float* __restrict__ W1, const float* __restrict__ b1,
        const float* __restrict__ W2, const float* __restrict__ b2,
        const float* __restrict__ temp){
    extern __shared__ float dyn[];
    float* sW1 = dyn;
    float* sW2 = dyn + 16384;
    float* se  = dyn + 32768;
    float* sh  = dyn + 33280;
    float* so  = dyn + 35328;
    float* ssc = dyn + 35840;
    int t = threadIdx.x;
    int b0 = blockIdx.x*8;
    const float4* W1v = (const float4*)W1; float4* s1v = (float4*)sW1;
    const float4* W2v = (const float4*)W2; float4* s2v = (float4*)sW2;
#pragma unroll
    for(int i=0;i<16;i++) s1v[t + i*256] = W1v[t + i*256];
#pragma unroll
    for(int i=0;i<16;i++) s2v[t + i*256] = W2v[t + i*256];
#pragma unroll
    for(int i=0;i<2;i++){ int idx = t + i*256; int bi = idx>>6, k = idx&63;
        se[idx] = emb[(size_t)cards[b0+bi]*64 + k]; }
    __syncthreads();
    float bb1 = b1[t];
#pragma unroll
    for(int bi=0;bi<8;bi++){
        float h = bb1;
#pragma unroll
        for(int k=0;k<64;k++) h = fmaf(se[bi*64+k], sW1[k*256+t], h);
        sh[bi*256+t] = fmaxf(h, 0.f);
    }
    __syncthreads();
    int d = t&63, q = t>>6;
    float bb2 = b2[d];
#pragma unroll
    for(int r=0;r<2;r++){
        int bi = q*2 + r;
        float o = bb2;
#pragma unroll 8
        for(int j=0;j<256;j++) o = fmaf(sh[bi*256+j], sW2[j*64+d], o);
        so[bi*64+d] = o;
    }
    __syncthreads();
    if (t < 8){
        float s = 0.f;
#pragma unroll
        for(int dd=0;dd<64;dd++){ float v = so[t*64+dd]; s = fmaf(v, v, s); }
        ssc[t] = temp[0]*LOG2E*rsqrtf(fmaxf(s, 1e-12f));
    }
    __syncthreads();
#pragma unroll
    for(int i=0;i<2;i++){ int idx = t + i*256; int bi = idx>>6;
        g_aBF[(size_t)b0*64 + idx] = __float2bfloat16_rn(so[idx]*ssc[bi]); }
}

// ---------------- kernel 2: init ----------------
__global__ void k_init(){
    int i = blockIdx.x*256 + threadIdx.x;   // 280 x 256 = 71680
    if (i < 65536) g_G[i] = 0.f;
    int j = i - 65536;
    if (j >= 0 && j < 4096) g_acc[j] = 0.f;
    int jj = j - 4096;
    if (jj >= 0 && jj < 1024) g_minL[jj] = 0xFFFFFFFFu;
    int kk = jj - 1024;
    if (kk >= 0 && kk < 1024) g_flag[kk] = 0;
}

// ---------------- staging helpers ----------------
// src = src0 + (row*rowstride + eoff) elements (bf16); dst rows padded to ES_STRIDE.
__device__ __forceinline__ void stage_E(const __nv_bfloat16* __restrict__ src0, size_t rowstride,
                                        int buf, unsigned eoff, uint32_t smbase, int tid){
    uint32_t eb = smbase + buf*ES_BYTES;
#pragma unroll
    for(int i=0;i<2;i++){
        int c = tid + i*256;
        int row = c>>3, seg = c&7;
        uint32_t dst = eb + row*ES_STRIDE + seg*16;
        const char* src = (const char*)src0 + ((size_t)row*rowstride + eoff)*2 + seg*16;
        asm volatile("cp.async.cg.shared.global [%0], [%1], 16;" :: "r"(dst), "l"(src));
    }
}
__device__ __forceinline__ void stage_adj(int buf, int j0, int rt, uint32_t smbase,
                                          const float* __restrict__ adj, int tid){
    uint32_t ab = smbase + ADJ_OFF + buf*ADJ_BYTES;
#pragma unroll
    for(int i=0;i<5;i++){
        unsigned idx = (unsigned)tid + i*256u;
        if (idx < 1088u){
            unsigned row = idx/17u, ch = idx - row*17u;
            size_t base = (size_t)(rt*64 + (int)row)*NJ + (unsigned)j0;
            size_t s = (base & ~(size_t)3) + ch*4u;
            uint32_t dst = ab + (row*ADJ_STRIDE + ch*4u)*4u;
            const float* src = adj + s;
            if (s + 4 <= NTOT){
                asm volatile("cp.async.cg.shared.global [%0], [%1], 16;" :: "r"(dst), "l"(src));
            } else {
#pragma unroll
                for(int e=0;e<4;e++){
                    float v = (s + e < NTOT) ? __ldcs(src + e) : 0.f;
                    asm volatile("st.shared.f32 [%0], %1;" :: "r"(dst + e*4u), "f"(v));
                }
            }
        }
    }
}

// ---------------- kernel 3: heterogeneous fat kernel ----------------
// grid (76,16), 256 thr, 4 CTAs/SM. role=(bx+by)&1: 0 = Z (logits->z,minL), 1 = ADJ (stats + adj@E).
__global__ void __launch_bounds__(256, 4) k_big(const float* __restrict__ adj){
    extern __shared__ __align__(16) char smB[];
    const uint32_t smbase = smem_u32(smB);
    int tid = threadIdx.x;
    int wid = tid>>5, lane = tid&31, g = lane>>2, tg = lane&3;
    int wr = wid&3, wc = wid>>2;
    int bx = blockIdx.x, rt = blockIdx.y;
    int role = (bx + rt) & 1;
    int jc = bx >> 1;
    int jstart = jc*CHUNK;
    int nvalid = NJ - jstart;
    int ntiles = (nvalid + 63)>>6; if (ntiles > TILES) ntiles = TILES;

    int r0l = wr*16 + g;
    int r0g = rt*64 + r0l;
    const uint32_t lmo = (uint32_t)((wc*32 + (lane&7))*ES_STRIDE + (lane>>3)*16);

    if (role == 0){
        // ================= Z path: z = sum 2^L, minL. No adj. =================
        uint32_t A[4][4];
        {
            const uint32_t* a0 = (const uint32_t*)(g_aBF + (size_t)r0g*64);
            const uint32_t* a1 = (const uint32_t*)(g_aBF + (size_t)(r0g+8)*64);
#pragma unroll
            for(int kt=0;kt<4;kt++){
                A[kt][0]=a0[kt*8+tg];   A[kt][1]=a1[kt*8+tg];
                A[kt][2]=a0[kt*8+tg+4]; A[kt][3]=a1[kt*8+tg+4];
            }
        }
        float Z[2]={0.f,0.f}, MN[2]={1e30f,1e30f};
        // E rows j0..j0+63: element offset = j0*64 in [j][k] layout (rowstride 64)
        stage_E(g_eB, 64, 0, (unsigned)jstart*64u, smbase, tid);
        asm volatile("cp.async.commit_group;" ::: "memory");

        for(int t=0;t<ntiles;t++){
            int j0 = jstart + (t<<6);
            int jv = NJ - j0; if (jv > 64) jv = 64;
            bool hasNext = (t+1) < ntiles;
            if (hasNext){
                stage_E(g_eB, 64, (t+1)&1, (unsigned)(j0+64)*64u, smbase, tid);
                asm volatile("cp.async.commit_group;" ::: "memory");
                asm volatile("cp.async.wait_group 1;" ::: "memory");
            } else {
                asm volatile("cp.async.wait_group 0;" ::: "memory");
            }
            __syncthreads();

            uint32_t esb = smbase + (t&1)*ES_BYTES + lmo;
            float acc[4][4];
#pragma unroll
            for(int nt=0;nt<4;nt++){ acc[nt][0]=0.f; acc[nt][1]=0.f; acc[nt][2]=0.f; acc[nt][3]=0.f; }
#pragma unroll
            for(int nt=0;nt<4;nt++){
                uint32_t ad = esb + nt*(8*ES_STRIDE);
                uint32_t b00,b01,b10,b11,b20,b21,b30,b31;
                LDM4(b00,b01,b10,b11, ad);
                LDM4(b20,b21,b30,b31, ad + 64);
                mma16816(acc[nt], A[0], b00, b01);
                mma16816(acc[nt], A[1], b10, b11);
                mma16816(acc[nt], A[2], b20, b21);
                mma16816(acc[nt], A[3], b30, b31);
            }
            if (jv == 64){
#pragma unroll
                for(int nt=0;nt<4;nt++){
                    Z[0] += ex2f_(acc[nt][0]) + ex2f_(acc[nt][1]);
                    Z[1] += ex2f_(acc[nt][2]) + ex2f_(acc[nt][3]);
                    MN[0] = fminf(MN[0], fminf(acc[nt][0], acc[nt][1]));
                    MN[1] = fminf(MN[1], fminf(acc[nt][2], acc[nt][3]));
                }
            } else {
#pragma unroll
                for(int nt=0;nt<4;nt++){
                    int c = wc*32 + nt*8 + tg*2;
                    if (c < jv){
                        Z[0] += ex2f_(acc[nt][0]); MN[0] = fminf(MN[0], acc[nt][0]);
                        Z[1] += ex2f_(acc[nt][2]); MN[1] = fminf(MN[1], acc[nt][2]);
                        if (c + 1 < jv){
                            Z[0] += ex2f_(acc[nt][1]); MN[0] = fminf(MN[0], acc[nt][1]);
                            Z[1] += ex2f_(acc[nt][3]); MN[1] = fminf(MN[1], acc[nt][3]);
                        }
                    }
                }
            }
            __syncthreads();
        }
#pragma unroll
        for(int r=0;r<2;r++){
#pragma unroll
            for(int off=1; off<4; off<<=1){
                Z[r] += __shfl_xor_sync(0xffffffffu, Z[r], off);
                MN[r] = fminf(MN[r], __shfl_xor_sync(0xffffffffu, MN[r], off));
            }
        }
        if (tg == 0){
#pragma unroll
            for(int r=0;r<2;r++){
                int row = r0g + r*8;
                atomicAdd(&g_acc[row*4+0], Z[r]);
                atomicMin(&g_minL[row], ford(MN[r]));
            }
        }
    } else {
        // ================= ADJ path: t2, t3, G += clip(adj)@E =================
        const int ash = (int)(((size_t)r0g*NJ + (unsigned)jstart) & 3);
        float accG[4][4];
#pragma unroll
        for(int nt=0;nt<4;nt++){ accG[nt][0]=0.f; accG[nt][1]=0.f; accG[nt][2]=0.f; accG[nt][3]=0.f; }
        float T2[2]={0.f,0.f}, T3[2]={0.f,0.f};

        stage_E(g_eBT, NJ_PAD, 0, (unsigned)jstart, smbase, tid);
        stage_adj(0, jstart, rt, smbase, adj, tid);
        asm volatile("cp.async.commit_group;" ::: "memory");

        for(int t=0;t<ntiles;t++){
            int j0 = jstart + (t<<6);
            int jv = NJ - j0; if (jv > 64) jv = 64;
            bool hasNext = (t+1) < ntiles;
            if (hasNext){
                stage_E(g_eBT, NJ_PAD, (t+1)&1, (unsigned)(j0+64), smbase, tid);
                stage_adj((t+1)&1, j0+64, rt, smbase, adj, tid);
                asm volatile("cp.async.commit_group;" ::: "memory");
                asm volatile("cp.async.wait_group 1;" ::: "memory");
            } else {
                asm volatile("cp.async.wait_group 0;" ::: "memory");
            }
            __syncthreads();

            uint32_t esb = smbase + (t&1)*ES_BYTES + lmo;
            const float* srow0 = (const float*)(smB + ADJ_OFF + (t&1)*ADJ_BYTES) + r0l*ADJ_STRIDE + ash;
            const float* srow1 = srow0 + 8*ADJ_STRIDE;

            uint32_t Af[4][4];
            if (jv == 64){
#pragma unroll
                for(int kt=0;kt<4;kt++){
                    int c = kt*16 + tg*2;
                    float y0 = fmaxf(srow0[c],   KL_EPS), y1 = fmaxf(srow0[c+1], KL_EPS);
                    float y2 = fmaxf(srow0[c+8], KL_EPS), y3 = fmaxf(srow0[c+9], KL_EPS);
                    float y4 = fmaxf(srow1[c],   KL_EPS), y5 = fmaxf(srow1[c+1], KL_EPS);
                    float y6 = fmaxf(srow1[c+8], KL_EPS), y7 = fmaxf(srow1[c+9], KL_EPS);
                    if (wc == 0){
                        T2[0] += (y0+y1) + (y2+y3);
                        T2[1] += (y4+y5) + (y6+y7);
                        T3[0] = fmaf(y0, lg2f_(y0), fmaf(y1, lg2f_(y1), fmaf(y2, lg2f_(y2), fmaf(y3, lg2f_(y3), T3[0]))));
                        T3[1] = fmaf(y4, lg2f_(y4), fmaf(y5, lg2f_(y5), fmaf(y6, lg2f_(y6), fmaf(y7, lg2f_(y7), T3[1]))));
                    }
                    CVTB2(Af[kt][0], y1, y0);
                    CVTB2(Af[kt][1], y5, y4);
                    CVTB2(Af[kt][2], y3, y2);
                    CVTB2(Af[kt][3], y7, y6);
                }
            } else {
#pragma unroll
                for(int kt=0;kt<4;kt++){
                    int c = kt*16 + tg*2;
                    float yv[8]; int cs[4] = {c, c+1, c+8, c+9};
#pragma unroll
                    for(int e=0;e<4;e++){
                        bool v = cs[e] < jv;
                        float a0 = v ? fmaxf(srow0[cs[e]], KL_EPS) : 0.f;
                        float a1 = v ? fmaxf(srow1[cs[e]], KL_EPS) : 0.f;
                        yv[e] = a0; yv[4+e] = a1;
                        if (v && wc == 0){
                            T2[0] += a0; T3[0] = fmaf(a0, lg2f_(a0), T3[0]);
                            T2[1] += a1; T3[1] = fmaf(a1, lg2f_(a1), T3[1]);
                        }
                    }
                    CVTB2(Af[kt][0], yv[1], yv[0]);
                    CVTB2(Af[kt][1], yv[5], yv[4]);
                    CVTB2(Af[kt][2], yv[3], yv[2]);
                    CVTB2(Af[kt][3], yv[7], yv[6]);
                }
            }
#pragma unroll
            for(int nt=0;nt<4;nt++){
                uint32_t ad = esb + nt*(8*ES_STRIDE);
                uint32_t b00,b01,b10,b11,b20,b21,b30,b31;
                LDM4(b00,b01,b10,b11, ad);
                LDM4(b20,b21,b30,b31, ad + 64);
                mma16816(accG[nt], Af[0], b00, b01);
                mma16816(accG[nt], Af[1], b10, b11);
                mma16816(accG[nt], Af[2], b20, b21);
                mma16816(accG[nt], Af[3], b30, b31);
            }
            __syncthreads();
        }
        if (wc == 0){
#pragma unroll
            for(int r=0;r<2;r++){
#pragma unroll
                for(int off=1; off<4; off<<=1){
                    T2[r] += __shfl_xor_sync(0xffffffffu, T2[r], off);
                    T3[r] += __shfl_xor_sync(0xffffffffu, T3[r], off);
                }
            }
            if (tg == 0){
#pragma unroll
                for(int r=0;r<2;r++){
                    int row = r0g + r*8;
                    atomicAdd(&g_acc[row*4+2], T2[r]);
                    atomicAdd(&g_acc[row*4+3], T3[r]);
                }
            }
        }
#pragma unroll
        for(int nt=0;nt<4;nt++){
#pragma unroll
            for(int e=0;e<4;e++){
                int row = r0g + ((e>>1)&1)*8;
                int n = wc*32 + nt*8 + tg*2 + (e&1);
                atomicAdd(&g_G[row*64 + n], accG[nt][e]);
            }
        }
    }
}

// ---------------- kernel 4: final combine ----------------
__global__ void k_final(const float* __restrict__ temp, float* __restrict__ out){
    __shared__ float red[256];
    int t = threadIdx.x;
    float local = 0.f;
#pragma unroll
    for(int i=0;i<4;i++){
        int b = t + i*256;
        const __nv_bfloat16* ar = g_aBF + (size_t)b*64;
        const float* Gr = g_G + (size_t)b*64;
        float t1 = 0.f;
#pragma unroll
        for(int k=0;k<64;k++) t1 = fmaf(__bfloat162float(ar[k]), Gr[k], t1);
        float Zb  = g_acc[b*4+0];
        float T2b = g_acc[b*4+2];
        float T3b = g_acc[b*4+3];
        unsigned mu = g_minL[b];
        float lse2 = lg2f_(Zb);
        float cross = t1 - lse2*T2b;
        g_lse2[b] = lse2; g_cross[b] = cross;
        if (forddec(mu) - lse2 < LG2_EPS + 0.02f) g_flag[b] = 1;
        local += T3b - cross;
    }
    red[t] = local;
    __syncthreads();
    for(int s=128;s;s>>=1){ if (t < s) red[t] += red[t+s]; __syncthreads(); }
    if (t == 0){
        float T = temp[0];
        out[0] = red[0]*(1.0f/(float)B) + T*T*0.01f;
    }
}

// ---------------- kernel 5: exact clipped fixup (cold, normally no-op) ----------------
__global__ void k_fixup(const float* __restrict__ adj, float* __restrict__ out){
    __shared__ int flags[128];
    __shared__ int any;
    __shared__ float a[64];
    __shared__ float red[256];
    int b0 = blockIdx.x*128;
    int t = threadIdx.x;
    if (t == 0) any = 0;
    __syncthreads();
    if (t < 128){ int f = g_flag[b0+t]; flags[t] = f; if (f) any = 1; }
    __syncthreads();
    if (!any) return;
    for(int r=0;r<128;r++){
        if (!flags[r]) continue;
        int b = b0 + r;
        if (t < 64) a[t] = __bfloat162float(g_aBF[b*64 + t]);
        __syncthreads();
        float lse2 = g_lse2[b];
        float cr = 0.f;
        for(int j=t; j<NJ; j+=256){
            float L = 0.f;
#pragma unroll
            for(int k=0;k<64;k++) L = fmaf(a[k], __bfloat162float(g_eB[(size_t)j*64 + k]), L);
            float y = fmaxf(adj[(size_t)b*NJ + j], KL_EPS);
            cr = fmaf(y, fmaxf(L - lse2, LG2_EPS), cr);
        }
        red[t] = cr; __syncthreads();
        for(int s=128;s;s>>=1){ if (t < s) red[t] += red[t+s]; __syncthreads(); }
        if (t == 0) atomicAdd(out, (g_cross[b] - red[0])*(1.0f/(float)B));
        __syncthreads();
    }
}

// ---------------- launch ----------------
extern "C" void kernel_launch(void* const* d_in, const int* in_sizes, int n_in,
                              void* d_out, int out_size){
    const int*   cards = (const int*)  d_in[0];
    const float* adj   = (const float*)d_in[1];
    const float* emb   = (const float*)d_in[2];
    const float* W1    = (const float*)d_in[3];
    const float* b1    = (const float*)d_in[4];
    const float* W2    = (const float*)d_in[5];
    const float* b2    = (const float*)d_in[6];
    const float* temp  = (const float*)d_in[7];

    cudaFuncSetAttribute(k_mlp, cudaFuncAttributeMaxDynamicSharedMemorySize, 143392);
    cudaFuncSetAttribute(k_big, cudaFuncAttributeMaxDynamicSharedMemorySize, SMEM_BIG);

    k_prep<<<NJ_PAD/64, 256>>>(emb);                                // idx 0
    k_mlp<<<128, 256, 143392>>>(cards, emb, W1, b1, W2, b2, temp);  // idx 1
    k_init<<<280, 256>>>();                                         // idx 2
    k_big<<<dim3(2*JC, 16), 256, SMEM_BIG>>>(adj);                  // idx 3 (ncu target)
    k_final<<<1, 256>>>(temp, (float*)d_out);                       // idx 4
    k_fixup<<<8, 256>>>(adj, (float*)d_out);                        // idx 5
}

// round 14
// speedup vs baseline: 2.3354x; 2.3354x over previous
#include <cuda_runtime.h>
#include <cuda_bf16.h>
#include <cstdint>

#define NCARDS 50000
#define NJ 49999
#define B 1024
#define NTOT4 204795904u       // B*NJ*4 bytes (fits u32)
#define JC 38
#define CHUNK 1344
#define NJ_PAD (JC*CHUNK)      // 51072
#define TILES 21
#define NCTA 608               // 38*16
#define LOG2E 1.4426950408889634f
#define KL_EPS 1e-7f
#define LG2_EPS -23.253496664211536f

// smem layout (bytes): E0[9216] E1[9216] ADJ0[17408] ADJ1[17408] = 53248
#define ES_STRIDE 144
#define ES_BYTES  9216
#define ADJ_STRIDE 68
#define ADJ_BYTES (64*ADJ_STRIDE*4)
#define ADJ_OFF   (2*ES_BYTES)
#define SMEM_G (ADJ_OFF + 2*ADJ_BYTES)   // 53248

// ---------------- device scratch ----------------
__device__ __nv_bfloat16 g_eB[(size_t)NJ_PAD*64];
__device__ __nv_bfloat16 g_aBF[B*64];
__device__ float    g_acc[B*4];
__device__ unsigned g_minL[B];
__device__ float    g_cross[B], g_lse2[B];
__device__ int      g_flag[B];
__device__ unsigned g_ctr;

// ---------------- helpers ----------------
__device__ __forceinline__ float ex2f_(float x){ float r; asm("ex2.approx.f32 %0, %1;" : "=f"(r) : "f"(x)); return r; }
__device__ __forceinline__ float lg2f_(float x){ float r; asm("lg2.approx.f32 %0, %1;" : "=f"(r) : "f"(x)); return r; }
__device__ __forceinline__ uint32_t smem_u32(const void* p){
    uint32_t a; asm("{ .reg .u64 t; cvta.to.shared.u64 t, %1; cvt.u32.u64 %0, t; }" : "=r"(a) : "l"(p)); return a; }
__device__ __forceinline__ unsigned ford(float f){
    int i = __float_as_int(f);
    return (i >= 0) ? ((unsigned)i | 0x80000000u) : ~(unsigned)i;
}
__device__ __forceinline__ float forddec(unsigned u){
    int i = (u & 0x80000000u) ? (int)(u & 0x7FFFFFFFu) : ~(int)u;
    return __int_as_float(i);
}
__device__ __forceinline__ void mma16816(float* c, const uint32_t* a, uint32_t b0, uint32_t b1){
    asm volatile("mma.sync.aligned.m16n8k16.row.col.f32.bf16.bf16.f32 "
        "{%0,%1,%2,%3}, {%4,%5,%6,%7}, {%8,%9}, {%0,%1,%2,%3};"
        : "+f"(c[0]), "+f"(c[1]), "+f"(c[2]), "+f"(c[3])
        : "r"(a[0]), "r"(a[1]), "r"(a[2]), "r"(a[3]), "r"(b0), "r"(b1));
}
#define LDM4(r0,r1,r2,r3,addr) \
    asm volatile("ldmatrix.sync.aligned.m8n8.x4.shared.b16 {%0,%1,%2,%3}, [%4];" \
        : "=r"(r0), "=r"(r1), "=r"(r2), "=r"(r3) : "r"(addr))

__device__ __forceinline__ void upd(float L, float y, float& z, float& t1, float& t2, float& t3, float& mn){
    y = fmaxf(y, KL_EPS);
    z += ex2f_(L);
    t1 = fmaf(y, L, t1);
    t2 += y;
    t3 = fmaf(y, lg2f_(y), t3);
    mn = fminf(mn, L);
}

// ---------------- kernel 0: normalize E[1:], 4 rows/warp ----------------
__global__ void k_enorm(const float* __restrict__ emb){
    int wid = threadIdx.x>>5, lane = threadIdx.x&31;
    int jb = (blockIdx.x*8 + wid)*4;
    float2 v[4]; float s[4];
#pragma unroll
    for(int r=0;r<4;r++){
        int j = jb + r;
        v[r] = make_float2(0.f, 0.f);
        if (j < NJ) v[r] = ((const float2*)emb)[(size_t)(j+1)*32 + lane];
        s[r] = v[r].x*v[r].x + v[r].y*v[r].y;
    }
#pragma unroll
    for(int o=16;o;o>>=1){
#pragma unroll
        for(int r=0;r<4;r++) s[r] += __shfl_xor_sync(0xffffffffu, s[r], o);
    }
#pragma unroll
    for(int r=0;r<4;r++){
        int j = jb + r;
        if (j < NJ_PAD){
            float inv = rsqrtf(fmaxf(s[r], 1e-12f));
            __nv_bfloat162 o2;
            o2.x = __float2bfloat16_rn(v[r].x*inv);
            o2.y = __float2bfloat16_rn(v[r].y*inv);
            ((__nv_bfloat162*)g_eB)[(size_t)j*32 + lane] = o2;
        }
    }
}

// ---------------- kernel 1: gather + MLP + l2norm, fold t*log2e ----------------
__global__ void __launch_bounds__(256) k_mlp(const int* __restrict__ cards, const float* __restrict__ emb,
        const float* __restrict__ W1, const float* __restrict__ b1,
        const float* __restrict__ W2, const float* __restrict__ b2,
        const float* __restrict__ temp){
    extern __shared__ float dyn[];
    float* sW1 = dyn;
    float* sW2 = dyn + 16384;
    float* se  = dyn + 32768;
    float* sh  = dyn + 33280;
    float* so  = dyn + 35328;
    float* ssc = dyn + 35840;
    int t = threadIdx.x;
    int b0 = blockIdx.x*8;
    const float4* W1v = (const float4*)W1; float4* s1v = (float4*)sW1;
    const float4* W2v = (const float4*)W2; float4* s2v = (float4*)sW2;
#pragma unroll
    for(int i=0;i<16;i++) s1v[t + i*256] = W1v[t + i*256];
#pragma unroll
    for(int i=0;i<16;i++) s2v[t + i*256] = W2v[t + i*256];
#pragma unroll
    for(int i=0;i<2;i++){ int idx = t + i*256; int bi = idx>>6, k = idx&63;
        se[idx] = emb[(size_t)cards[b0+bi]*64 + k]; }
    __syncthreads();
    float bb1 = b1[t];
#pragma unroll
    for(int bi=0;bi<8;bi++){
        float h = bb1;
#pragma unroll
        for(int k=0;k<64;k++) h = fmaf(se[bi*64+k], sW1[k*256+t], h);
        sh[bi*256+t] = fmaxf(h, 0.f);
    }
    __syncthreads();
    int d = t&63, q = t>>6;
    float bb2 = b2[d];
#pragma unroll
    for(int r=0;r<2;r++){
        int bi = q*2 + r;
        float o = bb2;
#pragma unroll 8
        for(int j=0;j<256;j++) o = fmaf(sh[bi*256+j], sW2[j*64+d], o);
        so[bi*64+d] = o;
    }
    __syncthreads();
    if (t < 8){
        float s = 0.f;
#pragma unroll
        for(int dd=0;dd<64;dd++){ float v = so[t*64+dd]; s = fmaf(v, v, s); }
        ssc[t] = temp[0]*LOG2E*rsqrtf(fmaxf(s, 1e-12f));
    }
    __syncthreads();
#pragma unroll
    for(int i=0;i<2;i++){ int idx = t + i*256; int bi = idx>>6;
        g_aBF[(size_t)b0*64 + idx] = __float2bfloat16_rn(so[idx]*ssc[bi]); }
}

// ---------------- kernel 2: init ----------------
__global__ void k_init(){
    int i = blockIdx.x*256 + threadIdx.x;   // 16x256 = 4096
    g_acc[i] = 0.f;
    if (i < B){ g_minL[i] = 0xFFFFFFFFu; g_flag[i] = 0; }
    if (i == 0) g_ctr = 0u;
}

// ---------------- staging state (per-thread, hoisted) ----------------
struct Stage {
    uint32_t offE[2];      // byte offset into g_eB (advance +8192/tile)
    uint32_t dstE[2];      // smem offset (add buf base)
    uint32_t offA[5];      // byte offset into adj (advance +256/tile)
    uint32_t dstA[5];      // smem offset within ADJ region
    uint32_t nA;           // valid adj chunks (4 or 5)
};

__device__ __forceinline__ void stage_issue(Stage& st, int buf, uint32_t smbase,
                                            const char* __restrict__ adjB){
    uint32_t eb = smbase + buf*ES_BYTES;
    const char* eB = (const char*)g_eB;
#pragma unroll
    for(int i=0;i<2;i++){
        asm volatile("cp.async.cg.shared.global [%0], [%1], 16;"
                     :: "r"(eb + st.dstE[i]), "l"(eB + st.offE[i]));
        st.offE[i] += 8192;
    }
    uint32_t ab = smbase + ADJ_OFF + buf*ADJ_BYTES;
#pragma unroll
    for(int i=0;i<5;i++){
        if (i < (int)st.nA){
            uint32_t o = st.offA[i];
            uint32_t d = ab + st.dstA[i];
            if (o + 16 <= NTOT4){
                asm volatile("cp.async.cg.shared.global [%0], [%1], 16;"
                             :: "r"(d), "l"(adjB + o));
            } else {
#pragma unroll
                for(int e=0;e<4;e++){
                    float v = 0.f;
                    if (o + e*4 + 4 <= NTOT4) v = __ldcs((const float*)(adjB + o + e*4));
                    asm volatile("st.shared.f32 [%0], %1;" :: "r"(d + e*4), "f"(v));
                }
            }
            st.offA[i] += 256;
        }
    }
    asm volatile("cp.async.commit_group;" ::: "memory");
}

// ---------------- kernel 3: HMMA GEMM + fused stats + last-CTA finalize ----------------
// grid (38,16), 256 thr, 4 CTAs/SM. M-tile 64, N-tile 64, warp grid 4m x 2n.
__global__ void __launch_bounds__(256, 4) k_gemm9(const float* __restrict__ adj,
                                                  const float* __restrict__ temp,
                                                  float* __restrict__ out){
    extern __shared__ __align__(16) char sm9[];
    const uint32_t smbase = smem_u32(sm9);
    int tid = threadIdx.x;
    int wid = tid>>5, lane = tid&31, g = lane>>2, tg = lane&3;
    int wr = wid&3, wc = wid>>2;
    int jc = blockIdx.x, rt = blockIdx.y;
    int jstart = jc*CHUNK;

    int r0l = wr*16 + g;
    int r0g = rt*64 + r0l;

    uint32_t A[4][4];
    {
        const uint32_t* a0 = (const uint32_t*)(g_aBF + (size_t)r0g*64);
        const uint32_t* a1 = (const uint32_t*)(g_aBF + (size_t)(r0g+8)*64);
#pragma unroll
        for(int kt=0;kt<4;kt++){
            A[kt][0]=a0[kt*8+tg];   A[kt][1]=a1[kt*8+tg];
            A[kt][2]=a0[kt*8+tg+4]; A[kt][3]=a1[kt*8+tg+4];
        }
    }
    const int ash = (int)(((size_t)r0g*NJ + (unsigned)jstart) & 3);
    const uint32_t lmo = (uint32_t)((wc*32 + (lane&7))*ES_STRIDE + (lane>>3)*16);
    const char* adjB = (const char*)adj;

    // hoisted staging offsets
    Stage st;
#pragma unroll
    for(int i=0;i<2;i++){
        int c = tid + i*256;
        int row = c>>3, seg = c&7;
        st.offE[i] = (uint32_t)(jstart + row)*128u + seg*16u;
        st.dstE[i] = (uint32_t)row*ES_STRIDE + seg*16u;
    }
    {
        int n = 0;
#pragma unroll
        for(int i=0;i<5;i++){
            int idx = tid + i*256;
            if (idx < 1088){
                int row = idx/17, ch = idx - row*17;
                size_t base = (size_t)(rt*64 + row)*NJ + (unsigned)jstart;   // elements
                st.offA[n] = (uint32_t)((base & ~(size_t)3)*4) + (uint32_t)ch*16u;
                st.dstA[n] = (uint32_t)row*(ADJ_STRIDE*4) + (uint32_t)ch*16u;
                n++;
            }
        }
        st.nA = (uint32_t)n;
    }

    float Z[2]={0.f,0.f}, T1[2]={0.f,0.f}, T2[2]={0.f,0.f}, T3[2]={0.f,0.f}, MN[2]={1e30f,1e30f};

    stage_issue(st, 0, smbase, adjB);

    if (jc != JC-1){
        // ======== fast path: 21 full tiles, no boundary logic ========
#pragma unroll 1
        for(int t=0;t<TILES;t++){
            if (t < TILES-1){
                stage_issue(st, (t+1)&1, smbase, adjB);
                asm volatile("cp.async.wait_group 1;" ::: "memory");
            } else {
                asm volatile("cp.async.wait_group 0;" ::: "memory");
            }
            __syncthreads();

            uint32_t esb = smbase + (t&1)*ES_BYTES + lmo;
            const float* srow0 = (const float*)(sm9 + ADJ_OFF + (t&1)*ADJ_BYTES) + r0l*ADJ_STRIDE + ash;
            const float* srow1 = srow0 + 8*ADJ_STRIDE;

            float acc[4][4];
#pragma unroll
            for(int nt=0;nt<4;nt++){ acc[nt][0]=0.f; acc[nt][1]=0.f; acc[nt][2]=0.f; acc[nt][3]=0.f; }
#pragma unroll
            for(int nt=0;nt<4;nt++){
                uint32_t ad = esb + nt*(8*ES_STRIDE);
                uint32_t b00,b01,b10,b11,b20,b21,b30,b31;
                LDM4(b00,b01,b10,b11, ad);
                LDM4(b20,b21,b30,b31, ad + 64);
                mma16816(acc[nt], A[0], b00, b01);
                mma16816(acc[nt], A[1], b10, b11);
                mma16816(acc[nt], A[2], b20, b21);
                mma16816(acc[nt], A[3], b30, b31);
            }
#pragma unroll
            for(int nt=0;nt<4;nt++){
                int c = wc*32 + nt*8 + tg*2;
                upd(acc[nt][0], srow0[c],   Z[0],T1[0],T2[0],T3[0],MN[0]);
                upd(acc[nt][1], srow0[c+1], Z[0],T1[0],T2[0],T3[0],MN[0]);
                upd(acc[nt][2], srow1[c],   Z[1],T1[1],T2[1],T3[1],MN[1]);
                upd(acc[nt][3], srow1[c+1], Z[1],T1[1],T2[1],T3[1],MN[1]);
            }
            __syncthreads();
        }
    } else {
        // ======== general path: last chunk (271 cols, 5 tiles) ========
        int nvalid = NJ - jstart;
        int ntiles = (nvalid + 63)>>6;
#pragma unroll 1
        for(int t=0;t<ntiles;t++){
            int j0 = jstart + (t<<6);
            int jv = NJ - j0; if (jv > 64) jv = 64;
            if (t < ntiles-1){
                stage_issue(st, (t+1)&1, smbase, adjB);
                asm volatile("cp.async.wait_group 1;" ::: "memory");
            } else {
                asm volatile("cp.async.wait_group 0;" ::: "memory");
            }
            __syncthreads();

            uint32_t esb = smbase + (t&1)*ES_BYTES + lmo;
            const float* srow0 = (const float*)(sm9 + ADJ_OFF + (t&1)*ADJ_BYTES) + r0l*ADJ_STRIDE + ash;
            const float* srow1 = srow0 + 8*ADJ_STRIDE;

            float acc[4][4];
#pragma unroll
            for(int nt=0;nt<4;nt++){ acc[nt][0]=0.f; acc[nt][1]=0.f; acc[nt][2]=0.f; acc[nt][3]=0.f; }
#pragma unroll
            for(int nt=0;nt<4;nt++){
                uint32_t ad = esb + nt*(8*ES_STRIDE);
                uint32_t b00,b01,b10,b11,b20,b21,b30,b31;
                LDM4(b00,b01,b10,b11, ad);
                LDM4(b20,b21,b30,b31, ad + 64);
                mma16816(acc[nt], A[0], b00, b01);
                mma16816(acc[nt], A[1], b10, b11);
                mma16816(acc[nt], A[2], b20, b21);
                mma16816(acc[nt], A[3], b30, b31);
            }
#pragma unroll
            for(int nt=0;nt<4;nt++){
                int c = wc*32 + nt*8 + tg*2;
                if (c < jv){
                    upd(acc[nt][0], srow0[c], Z[0],T1[0],T2[0],T3[0],MN[0]);
                    upd(acc[nt][2], srow1[c], Z[1],T1[1],T2[1],T3[1],MN[1]);
                    if (c + 1 < jv){
                        upd(acc[nt][1], srow0[c+1], Z[0],T1[0],T2[0],T3[0],MN[0]);
                        upd(acc[nt][3], srow1[c+1], Z[1],T1[1],T2[1],T3[1],MN[1]);
                    }
                }
            }
            __syncthreads();
        }
    }

    // reduce over tg lanes, atomic merge
#pragma unroll
    for(int r=0;r<2;r++){
#pragma unroll
        for(int off=1; off<4; off<<=1){
            Z[r]  += __shfl_xor_sync(0xffffffffu, Z[r],  off);
            T1[r] += __shfl_xor_sync(0xffffffffu, T1[r], off);
            T2[r] += __shfl_xor_sync(0xffffffffu, T2[r], off);
            T3[r] += __shfl_xor_sync(0xffffffffu, T3[r], off);
            MN[r]  = fminf(MN[r], __shfl_xor_sync(0xffffffffu, MN[r], off));
        }
    }
    if (tg == 0){
#pragma unroll
        for(int r=0;r<2;r++){
            int row = r0g + r*8;
            atomicAdd(&g_acc[row*4+0], Z[r]);
            atomicAdd(&g_acc[row*4+1], T1[r]);
            atomicAdd(&g_acc[row*4+2], T2[r]);
            atomicAdd(&g_acc[row*4+3], T3[r]);
            atomicMin(&g_minL[row], ford(MN[r]));
        }
    }

    // ---- last CTA finalizes ----
    __threadfence();
    __shared__ unsigned s_last;
    if (tid == 0) s_last = (atomicAdd(&g_ctr, 1u) == NCTA-1) ? 1u : 0u;
    __syncthreads();
    if (!s_last) return;

    float* red = (float*)sm9;
    float T = temp[0];
    float local = 0.f;
#pragma unroll
    for(int i=0;i<4;i++){
        int b = tid + i*256;
        float Zb, T1b, T2b, T3b; unsigned mu;
        asm("ld.global.cg.f32 %0, [%1];" : "=f"(Zb)  : "l"(&g_acc[b*4+0]));
        asm("ld.global.cg.f32 %0, [%1];" : "=f"(T1b) : "l"(&g_acc[b*4+1]));
        asm("ld.global.cg.f32 %0, [%1];" : "=f"(T2b) : "l"(&g_acc[b*4+2]));
        asm("ld.global.cg.f32 %0, [%1];" : "=f"(T3b) : "l"(&g_acc[b*4+3]));
        asm("ld.global.cg.u32 %0, [%1];" : "=r"(mu)  : "l"(&g_minL[b]));
        float lse2 = lg2f_(Zb);
        float cross = T1b - lse2*T2b;
        g_lse2[b] = lse2;
        g_cross[b] = cross;
        if (forddec(mu) - lse2 < LG2_EPS + 0.02f) g_flag[b] = 1;
        local += T3b - cross;
    }
    red[tid] = local;
    __syncthreads();
    for(int s=128;s;s>>=1){ if (tid < s) red[tid] += red[tid+s]; __syncthreads(); }
    if (tid == 0) out[0] = red[0]*(1.0f/(float)B) + T*T*0.01f;
}

// ---------------- kernel 4: exact clipped fixup (cold, normally no-op) ----------------
__global__ void k_fixup(const float* __restrict__ adj, float* __restrict__ out){
    __shared__ int flags[128];
    __shared__ int any;
    __shared__ float a[64];
    __shared__ float red[256];
    int b0 = blockIdx.x*128;
    int t = threadIdx.x;
    if (t == 0) any = 0;
    __syncthreads();
    if (t < 128){ int f = g_flag[b0+t]; flags[t] = f; if (f) any = 1; }
    __syncthreads();
    if (!any) return;
    for(int r=0;r<128;r++){
        if (!flags[r]) continue;
        int b = b0 + r;
        if (t < 64) a[t] = __bfloat162float(g_aBF[b*64 + t]);
        __syncthreads();
        float lse2 = g_lse2[b];
        float cr = 0.f;
        for(int j=t; j<NJ; j+=256){
            float L = 0.f;
#pragma unroll
            for(int k=0;k<64;k++) L = fmaf(a[k], __bfloat162float(g_eB[(size_t)j*64 + k]), L);
            float y = fmaxf(adj[(size_t)b*NJ + j], KL_EPS);
            cr = fmaf(y, fmaxf(L - lse2, LG2_EPS), cr);
        }
        red[t] = cr; __syncthreads();
        for(int s=128;s;s>>=1){ if (t < s) red[t] += red[t+s]; __syncthreads(); }
        if (t == 0) atomicAdd(out, (g_cross[b] - red[0])*(1.0f/(float)B));
        __syncthreads();
    }
}

// ---------------- launch ----------------
extern "C" void kernel_launch(void* const* d_in, const int* in_sizes, int n_in,
                              void* d_out, int out_size){
    const int*   cards = (const int*)  d_in[0];
    const float* adj   = (const float*)d_in[1];
    const float* emb   = (const float*)d_in[2];
    const float* W1    = (const float*)d_in[3];
    const float* b1    = (const float*)d_in[4];
    const float* W2    = (const float*)d_in[5];
    const float* b2    = (const float*)d_in[6];
    const float* temp  = (const float*)d_in[7];

    cudaFuncSetAttribute(k_mlp,   cudaFuncAttributeMaxDynamicSharedMemorySize, 143392);
    cudaFuncSetAttribute(k_gemm9, cudaFuncAttributeMaxDynamicSharedMemorySize, SMEM_G);

    k_enorm<<<1596, 256>>>(emb);                                   // idx 0
    k_mlp<<<128, 256, 143392>>>(cards, emb, W1, b1, W2, b2, temp); // idx 1
    k_init<<<16, 256>>>();                                         // idx 2
    k_gemm9<<<dim3(JC, 16), 256, SMEM_G>>>(adj, temp, (float*)d_out); // idx 3 (ncu target)
    k_fixup<<<8, 256>>>(adj, (float*)d_out);                       // idx 4
}